// round 16
// baseline (speedup 1.0000x reference)
#include <cuda_runtime.h>
#include <math.h>

#define S_DIM 512
#define B_DIM 32
#define T_DIM 1024
#define E_DIM 512
#define Q_DIM 128
#define SPB   16         // s-rows per consumer block
#define TCH   16         // staged t-chunk (rows in shared; 128B sw2 rows)
#define CUT   12.0f      // exponent cutoff: exp(-12) ~ 6e-6 (validated)
#define QCH   128        // s-rows per producer quarter
#define NQ    4          // producer quarters per batch
#define NTHR  256

// Scratch (allocation-free rule: __device__ globals).
__device__ float2 g_ms[B_DIM * S_DIM];     // (mean, std), [b][s]
__device__ float  g_qsum[B_DIM * NQ];      // own-quarter mean_raw total
__device__ int    g_ftot[B_DIM * NQ];      // quarter total published (monotone)
__device__ int    g_fdone[B_DIM * NQ];     // quarter means written (monotone)

// Packed f32x2 helpers (Blackwell FFMA2 — only reachable via PTX).
static __device__ __forceinline__ unsigned long long pack2f(float a, float b) {
    unsigned long long r;
    asm("mov.b64 %0, {%1, %2};" : "=l"(r) : "f"(a), "f"(b));
    return r;
}
static __device__ __forceinline__ unsigned long long fma2(
    unsigned long long a, unsigned long long b, unsigned long long c) {
    unsigned long long d;
    asm("fma.rn.f32x2 %0, %1, %2, %3;" : "=l"(d) : "l"(a), "l"(b), "l"(c));
    return d;
}
static __device__ __forceinline__ int ld_acq(const int* p) {
    int v;
    asm volatile("ld.acquire.gpu.global.b32 %0, [%1];" : "=r"(v) : "l"(p) : "memory");
    return v;
}
static __device__ __forceinline__ void st_rel(int* p, int v) {
    asm volatile("st.release.gpu.global.b32 [%0], %1;" :: "l"(p), "r"(v) : "memory");
}
static __device__ __forceinline__ void cp_async16(unsigned smem_addr, const void* g) {
    asm volatile("cp.async.ca.shared.global [%0], [%1], 16;"
                 :: "r"(smem_addr), "l"(g) : "memory");
}

// ---------------------------------------------------------------------------
// ONE fused kernel. Grid (B, 32), 256 threads, 4 blocks/SM forced.
// Blocks y < NQ FIRST produce quarter y (dots + exp + chained scan), then ALL
// blocks consume chunk y (s0 = y*SPB): smem-staged windowed Gaussian GEMM.
// ---------------------------------------------------------------------------
__global__ void __launch_bounds__(NTHR, 4) ga_fused(
    const float* __restrict__ q,     // [S,B,Q]
    const float* __restrict__ emb,   // [T,B,E]
    const float* __restrict__ mask,  // [T,B]
    const float* __restrict__ pos,   // [S,B]
    const float* __restrict__ W,     // [2,Q]
    const float* __restrict__ bias,  // [2]
    float* __restrict__ out_ctx,     // [S,B,E]
    float* __restrict__ out_mean)    // [S,B]
{
    const int b    = blockIdx.x;
    const int y    = blockIdx.y;          // chunk id 0..31
    const int tid  = threadIdx.x;
    const int warp = tid >> 5;
    const int lane = tid & 31;

    __shared__ float tile[TCH * E_DIM];               // 32 KB staged rows
    __shared__ float smean[SPB];
    __shared__ float sstd[SPB];
    __shared__ unsigned long long sw2[SPB][TCH];      // packed (w,w), 128B rows
    __shared__ float p_mr[QCH];
    __shared__ float p_sd[QCH];
    __shared__ float wsum[4];
    __shared__ float sprev;

    if (y < NQ) {
        // ============ PRODUCER quarter y (8 warps x 16 rows) ==============
        const int s_base = y * QCH;

        float4 a0 = ((const float4*)W)[lane];
        float4 a1 = ((const float4*)W)[32 + lane];
        float b0 = bias[0], b1 = bias[1];

        #pragma unroll
        for (int g = 0; g < 2; g++) {
            int r0 = warp * 16 + g * 8;
            float v[16];
            #pragma unroll
            for (int k = 0; k < 8; k++) {
                int s = s_base + r0 + k;
                float4 x = ((const float4*)q)[((size_t)s * B_DIM + b) * 32 + lane];
                v[2 * k]     = x.x * a0.x + x.y * a0.y + x.z * a0.z + x.w * a0.w;
                v[2 * k + 1] = x.x * a1.x + x.y * a1.y + x.z * a1.z + x.w * a1.w;
            }
            // Multi-value butterfly: 16 sums reduced in 16 SHFLs.
            #pragma unroll
            for (int i = 0; i < 8; i++) {
                float send = (lane & 16) ? v[i] : v[i + 8];
                float recv = __shfl_xor_sync(0xFFFFFFFFu, send, 16);
                v[i] = ((lane & 16) ? v[i + 8] : v[i]) + recv;
            }
            #pragma unroll
            for (int i = 0; i < 4; i++) {
                float send = (lane & 8) ? v[i] : v[i + 4];
                float recv = __shfl_xor_sync(0xFFFFFFFFu, send, 8);
                v[i] = ((lane & 8) ? v[i + 4] : v[i]) + recv;
            }
            #pragma unroll
            for (int i = 0; i < 2; i++) {
                float send = (lane & 4) ? v[i] : v[i + 2];
                float recv = __shfl_xor_sync(0xFFFFFFFFu, send, 4);
                v[i] = ((lane & 4) ? v[i + 2] : v[i]) + recv;
            }
            {
                float send = (lane & 2) ? v[0] : v[1];
                float recv = __shfl_xor_sync(0xFFFFFFFFu, send, 2);
                v[0] = ((lane & 2) ? v[1] : v[0]) + recv;
            }
            v[0] += __shfl_xor_sync(0xFFFFFFFFu, v[0], 1);

            int m = (lane >> 1) & 15;     // row k=m>>1, output j=m&1
            int k = m >> 1;
            int j = m & 1;
            float e = __expf(v[0] + (j ? b1 : b0));
            if (!(lane & 1)) {
                if (j == 0) p_mr[r0 + k] = e;
                else        p_sd[r0 + k] = e;
            }
        }
        __syncthreads();

        // In-quarter scan on threads 0-127.
        float v = 0.0f;
        if (tid < QCH) {
            v = p_mr[tid];
            #pragma unroll
            for (int off = 1; off < 32; off <<= 1) {
                float yv = __shfl_up_sync(0xFFFFFFFFu, v, off);
                if (lane >= off) v += yv;
            }
            if (lane == 31) wsum[warp] = v;
        }
        __syncthreads();

        // Publish own total immediately; then gather previous quarters.
        if (tid == 0) {
            float tot = wsum[0] + wsum[1] + wsum[2] + wsum[3];
            g_qsum[b * NQ + y] = tot;
            __threadfence();
            st_rel(&g_ftot[b * NQ + y], 1);
            float prev = 0.0f;
            for (int qq = 0; qq < y; qq++) {
                while (!ld_acq(&g_ftot[b * NQ + qq])) __nanosleep(32);
                prev += g_qsum[b * NQ + qq];
            }
            sprev = prev;
        }
        __syncthreads();

        if (tid < QCH) {
            float base = sprev;
            #pragma unroll
            for (int w = 0; w < 3; w++) if (w < warp) base += wsum[w];
            int s = s_base + tid;
            float mean = pos[(size_t)s * B_DIM + b] + (base + v) * 0.05f;
            g_ms[b * S_DIM + s] = make_float2(mean, p_sd[tid]);
            out_mean[(size_t)s * B_DIM + b] = mean;
        }
        __syncthreads();
        if (tid == 0) {
            __threadfence();
            st_rel(&g_fdone[b * NQ + y], 1);
        }
        __syncthreads();   // smem reuse edge before consumer phase
    }

    // ================= CONSUMER (all blocks): chunk y =================
    const int s0      = y * SPB;
    const int half    = tid >> 7;         // 0: si 0-7, 1: si 8-15
    const int h       = tid & 127;        // e-slot: floats [4h, 4h+4)
    const int quarter = y >> 3;

    if (tid == 0) {
        while (!ld_acq(&g_fdone[b * NQ + quarter])) __nanosleep(64);
    }
    __syncthreads();

    if (tid < SPB) {
        float2 ms = g_ms[b * S_DIM + s0 + tid];
        smean[tid] = ms.x;
        sstd[tid]  = ms.y;
    }
    __syncthreads();

    // Warp-parallel union window (lane si=lane&15, shfl min/max reduce).
    int tlo, thi;
    {
        int si = lane & 15;
        float mean = smean[si];
        float hw   = sqrtf(CUT / sstd[si]);
        int lo = (int)fmaxf(0.0f, ceilf(mean - hw));
        int hi = (int)fminf((float)(T_DIM - 1), floorf(mean + hw));
        #pragma unroll
        for (int off = 8; off; off >>= 1) {
            lo = min(lo, __shfl_xor_sync(0xFFFFFFFFu, lo, off));
            hi = max(hi, __shfl_xor_sync(0xFFFFFFFFu, hi, off));
        }
        tlo = lo; thi = hi;
    }

    ulonglong2 acc[8];
    #pragma unroll
    for (int i = 0; i < 8; i++) { acc[i].x = acc[i].y = 0ull; }

    const unsigned tile_base = (unsigned)__cvta_generic_to_shared(tile);

    for (int tb = tlo; tb <= thi; tb += TCH) {
        int n  = min(TCH, thi - tb + 1);
        int n2 = (n + 1) & ~1;            // even row count for the pair loop
        __syncthreads();   // protect tile + sw2 reuse across chunks

        // Stage n2 rows (2 KB each): threads split row-pairs, 16B cp.async.
        // Row index clamped to T_DIM-1 (pad rows get weight 0; data finite).
        for (int j = half; j < n2; j += 2) {
            int t = min(tb + j, T_DIM - 1);
            const float* src = emb + ((size_t)t * B_DIM + b) * E_DIM + h * 4;
            cp_async16(tile_base + (unsigned)(j * E_DIM + h * 4) * 4u, src);
        }
        asm volatile("cp.async.commit_group;" ::: "memory");

        // Weights (overlap the copies): 256 threads fill 16x16 slots.
        {
            int si = tid >> 4;                // 0..15
            int tj = tid & (TCH - 1);
            float wv = 0.0f;
            if (tj < n) {
                int   t = tb + tj;
                float d = smean[si] - (float)t;
                wv = __expf(-sstd[si] * d * d) * mask[(size_t)t * B_DIM + b];
            }
            sw2[si][tj] = pack2f(wv, wv);
        }

        asm volatile("cp.async.wait_group 0;" ::: "memory");
        __syncthreads();

        // Pair-row FMA from shared: per 2 rows, 2 LDS.128 (v0,v1) +
        // 8 broadcast LDS.128 (weight pairs) + 32 FFMA2.
        #pragma unroll 4
        for (int j = 0; j < n2; j += 2) {
            ulonglong2 v0 = *(const ulonglong2*)&tile[j * E_DIM + h * 4];
            ulonglong2 v1 = *(const ulonglong2*)&tile[(j + 1) * E_DIM + h * 4];
            #pragma unroll
            for (int r = 0; r < 8; r++) {
                ulonglong2 wp = *(const ulonglong2*)&sw2[half * 8 + r][j];
                acc[r].x = fma2(v0.x, wp.x, acc[r].x);
                acc[r].y = fma2(v0.y, wp.x, acc[r].y);
                acc[r].x = fma2(v1.x, wp.y, acc[r].x);
                acc[r].y = fma2(v1.y, wp.y, acc[r].y);
            }
        }
    }

    float* op = out_ctx + ((size_t)(s0 + half * 8) * B_DIM + b) * E_DIM + h * 4;
    #pragma unroll
    for (int r = 0; r < 8; r++) {
        *(ulonglong2*)op = acc[r];
        op += (size_t)B_DIM * E_DIM;
    }
}

// ---------------------------------------------------------------------------
extern "C" void kernel_launch(void* const* d_in, const int* in_sizes, int n_in,
                              void* d_out, int out_size) {
    const float* query = (const float*)d_in[0];  // [S,B,Q]
    const float* emb   = (const float*)d_in[1];  // [T,B,E]
    const float* mask  = (const float*)d_in[2];  // [T,B]
    const float* pos   = (const float*)d_in[3];  // [S,B]
    const float* W     = (const float*)d_in[4];  // [2,Q]
    const float* bias  = (const float*)d_in[5];  // [2]

    float* out_ctx  = (float*)d_out;                                  // [S,B,E]
    float* out_mean = (float*)d_out + (size_t)S_DIM * B_DIM * E_DIM;  // [S,B]

    dim3 grid(B_DIM, S_DIM / SPB);   // 1024 blocks; first 128 also produce
    ga_fused<<<grid, NTHR>>>(query, emb, mask, pos, W, bias, out_ctx, out_mean);
}